// round 1
// baseline (speedup 1.0000x reference)
#include <cuda_runtime.h>
#include <math.h>
#include <stdint.h>

#define N_SAMP 2048
#define MDIMS  36
#define REP    10
#define FEAT   360           // 36*10
#define DENSE_N 16384        // 256*8*8

// ---------------- scratch (static device globals; no runtime alloc) ----------
__device__ float g_JD[286];                         // block-diag J_l, offsets below
__device__ float g_item[N_SAMP * FEAT];             // 2.9 MB
__device__ float g_h0[N_SAMP * 16384];              // 134 MB  [n,256,8,8]
__device__ float g_h1[N_SAMP * 128 * 256];          // 268 MB  [n,128,16,16]
__device__ float g_h2[N_SAMP * 64 * 1024];          // 536 MB  [n,64,32,32]

__device__ __constant__ int c_off[7] = {0, 1, 10, 35, 84, 165, 286};

// ---------------- J_l = Re(C d^l(pi/2) C^H) computed on device ---------------
__device__ double dfact(int n) { double r = 1.0; for (int i = 2; i <= n; i++) r *= (double)i; return r; }

__device__ double small_d(int l, int mp, int m) {
    const double ch = 0.70710678118654752440;  // cos(pi/4)
    const double sh = 0.70710678118654752440;  // sin(pi/4)
    double pref = sqrt(dfact(l + mp) * dfact(l - mp) * dfact(l + m) * dfact(l - m));
    int smin = max(0, m - mp);
    int smax = min(l + m, l - mp);
    double tot = 0.0;
    for (int s = smin; s <= smax; s++) {
        double sign = ((mp - m + s) & 1) ? -1.0 : 1.0;
        double denom = dfact(l + m - s) * dfact(s) * dfact(mp - m + s) * dfact(l - mp - s);
        tot += sign / denom * pow(ch, (double)(2 * l + m - mp - 2 * s)) * pow(sh, (double)(mp - m + 2 * s));
    }
    return pref * tot;
}

__device__ void c2r_row(int l, int i, int* col, double* re, double* im, int* cnt) {
    int m = i - l;
    const double s = 0.70710678118654752440;  // 1/sqrt(2)
    if (m < 0) {
        double sgn = (m & 1) ? -1.0 : 1.0;     // (-1)^m
        col[0] = l + m; re[0] = 0.0; im[0] = s;
        col[1] = l - m; re[1] = 0.0; im[1] = -sgn * s;
        *cnt = 2;
    } else if (m == 0) {
        col[0] = l; re[0] = 1.0; im[0] = 0.0; *cnt = 1;
    } else {
        double sgn = (m & 1) ? -1.0 : 1.0;
        col[0] = l - m; re[0] = s;        im[0] = 0.0;
        col[1] = l + m; re[1] = sgn * s;  im[1] = 0.0;
        *cnt = 2;
    }
}

__global__ void init_jd_kernel() {
    int idx = threadIdx.x;
    if (idx >= 286) return;
    int l = 0;
    while (idx >= c_off[l + 1]) l++;
    int e = idx - c_off[l];
    int sz = 2 * l + 1;
    int i = e / sz, j = e % sz;
    int ca_c[2], cb_c[2], na, nb;
    double ca_re[2], ca_im[2], cb_re[2], cb_im[2];
    c2r_row(l, i, ca_c, ca_re, ca_im, &na);
    c2r_row(l, j, cb_c, cb_re, cb_im, &nb);
    double acc = 0.0;
    for (int a = 0; a < na; a++)
        for (int b = 0; b < nb; b++) {
            double cross = ca_re[a] * cb_re[b] + ca_im[a] * cb_im[b];  // Re(ca * conj(cb)), d real
            if (cross != 0.0)
                acc += cross * small_d(l, ca_c[a] - l, cb_c[b] - l);
        }
    g_JD[idx] = (float)acc;
}

// ---------------- Wigner apply: item[n,36,10] = blockdiag(D_l(angles_n)) @ item_rep --------
__device__ __forceinline__ void zrot_apply(const float* v, int sz, int l, float ang, float* out) {
    for (int i = 0; i < sz; i++) {
        float f = (float)(l - i);
        float s, c;
        sincosf(f * ang, &s, &c);
        out[i] = c * v[i] + s * v[sz - 1 - i];
    }
}

__global__ void wigner_kernel(const float* __restrict__ angles, const float* __restrict__ item_rep) {
    int t = blockIdx.x * blockDim.x + threadIdx.x;
    if (t >= N_SAMP * REP) return;
    int n = t / REP, r = t % REP;
    float a0 = angles[n * 3 + 0];
    float a1 = angles[n * 3 + 1];
    float a2 = angles[n * 3 + 2];
    float v[11], w[11];
    for (int l = 0; l <= 5; l++) {
        int sz = 2 * l + 1;
        const float* J = &g_JD[c_off[l]];
        for (int i = 0; i < sz; i++) v[i] = item_rep[(l * l + i) * REP + r];
        zrot_apply(v, sz, l, a2, w);                         // Zc
        for (int i = 0; i < sz; i++) {                       // J
            float s = 0.f;
            for (int j = 0; j < sz; j++) s += J[i * sz + j] * w[j];
            v[i] = s;
        }
        zrot_apply(v, sz, l, a1, w);                         // Zb
        for (int i = 0; i < sz; i++) {                       // J
            float s = 0.f;
            for (int j = 0; j < sz; j++) s += J[i * sz + j] * w[j];
            v[i] = s;
        }
        zrot_apply(v, sz, l, a0, w);                         // Za
        for (int i = 0; i < sz; i++)
            g_item[n * FEAT + (l * l + i) * REP + r] = w[i];
    }
}

// ---------------- dense: h0 = relu(item @ w0 + b0), [2048,360]x[360,16384] ----------------
__global__ __launch_bounds__(256) void dense_kernel(const float* __restrict__ A,
                                                    const float* __restrict__ B,
                                                    const float* __restrict__ bias,
                                                    float* __restrict__ C) {
    __shared__ float As[8][68];  // padded: k-row stride 68 (16B-aligned, conflict-free)
    __shared__ float Bs[8][64];
    int tid = threadIdx.x;
    int bn = blockIdx.x, bm = blockIdx.y;
    int tx = tid & 15, ty = tid >> 4;
    float acc[4][4];
#pragma unroll
    for (int i = 0; i < 4; i++)
#pragma unroll
        for (int j = 0; j < 4; j++) acc[i][j] = 0.f;

    int ka = tid & 7, ma = tid >> 3;      // A-load: 32 rows x 8 k per pass
    int kb = tid >> 6, nb = tid & 63;     // B-load: 4 k-rows x 64 n per pass
    const float* Ab = A + (size_t)(bm * 64) * FEAT;
    const float* Bb = B + bn * 64;

    for (int k0 = 0; k0 < FEAT; k0 += 8) {
        __syncthreads();
        As[ka][ma]      = Ab[(size_t)ma * FEAT + k0 + ka];
        As[ka][ma + 32] = Ab[(size_t)(ma + 32) * FEAT + k0 + ka];
        Bs[kb][nb]      = Bb[(size_t)(k0 + kb) * DENSE_N + nb];
        Bs[kb + 4][nb]  = Bb[(size_t)(k0 + kb + 4) * DENSE_N + nb];
        __syncthreads();
#pragma unroll
        for (int k = 0; k < 8; k++) {
            float4 a4 = *(const float4*)&As[k][ty * 4];
            float4 b4 = *(const float4*)&Bs[k][tx * 4];
            float av[4] = {a4.x, a4.y, a4.z, a4.w};
            float bv[4] = {b4.x, b4.y, b4.z, b4.w};
#pragma unroll
            for (int i = 0; i < 4; i++)
#pragma unroll
                for (int j = 0; j < 4; j++) acc[i][j] += av[i] * bv[j];
        }
    }
    float4 bi4 = *(const float4*)&bias[bn * 64 + tx * 4];
    float bv[4] = {bi4.x, bi4.y, bi4.z, bi4.w};
#pragma unroll
    for (int i = 0; i < 4; i++) {
        int m = bm * 64 + ty * 4 + i;
        float4 o;
        o.x = fmaxf(acc[i][0] + bv[0], 0.f);
        o.y = fmaxf(acc[i][1] + bv[1], 0.f);
        o.z = fmaxf(acc[i][2] + bv[2], 0.f);
        o.w = fmaxf(acc[i][3] + bv[3], 0.f);
        *(float4*)&C[(size_t)m * DENSE_N + bn * 64 + tx * 4] = o;
    }
}

// ---------------- transposed conv (k=4, s=2, SAME) via parity decomposition --------------
// out[n,co,2q+r] = sum_{ci,dy,dx} w[co,ci,2dy+ry,2dx+rx] * in[n,ci, q+dy-(1-r)]
template <int CIN, int COUT, int HIN, bool RELU>
__global__ __launch_bounds__(256) void deconv_kernel(const float* __restrict__ in,
                                                     const float* __restrict__ wgt,
                                                     float* __restrict__ out) {
    const int HOUT = HIN * 2;
    const int TILES_X = HIN / 8;
    int n = blockIdx.x;
    int co_blk = blockIdx.y;
    int tile = blockIdx.z;
    int tqy = (tile / TILES_X) * 8;
    int tqx = (tile % TILES_X) * 8;

    __shared__ float sin_[8 * 100];        // 8 ci x padded 10x10 input tile
    __shared__ float wsm[8 * 64 * 16];     // [ci][co][tap]

    int tid = threadIdx.x;
    int co_g = tid >> 4;                   // 0..15 -> 4 co each
    int q_g = tid & 15;                    // 0..15 -> 2x2 input positions
    int qy0 = (q_g >> 2) * 2;
    int qx0 = (q_g & 3) * 2;

    float acc[64];
#pragma unroll
    for (int i = 0; i < 64; i++) acc[i] = 0.f;

    const float* in_n = in + (size_t)n * CIN * HIN * HIN;
    const float4* wg4 = (const float4*)wgt;
    float4* ws4 = (float4*)wsm;

    for (int ci0 = 0; ci0 < CIN; ci0 += 8) {
        __syncthreads();
        // input tile (zero-padded halo)
        for (int idx = tid; idx < 800; idx += 256) {
            int ci = idx / 100, rem = idx % 100;
            int py = rem / 10, px = rem % 10;
            int y = tqy + py - 1, x = tqx + px - 1;
            float val = 0.f;
            if (y >= 0 && y < HIN && x >= 0 && x < HIN)
                val = in_n[(ci0 + ci) * HIN * HIN + y * HIN + x];
            sin_[idx] = val;
        }
        // weights: 8 ci x 64 co x 16 taps (float4 vectorized)
        for (int idx = tid; idx < 2048; idx += 256) {
            int ci = idx >> 8;
            int rr = idx & 255;
            int co = rr >> 2;
            int t4 = rr & 3;
            ws4[idx] = wg4[((size_t)(co_blk * 64 + co) * CIN + ci0 + ci) * 4 + t4];
        }
        __syncthreads();
#pragma unroll 1
        for (int ci = 0; ci < 8; ci++) {
            float iv[4][4];
#pragma unroll
            for (int yy = 0; yy < 4; yy++)
#pragma unroll
                for (int xx = 0; xx < 4; xx++)
                    iv[yy][xx] = sin_[ci * 100 + (qy0 + yy) * 10 + (qx0 + xx)];
#pragma unroll
            for (int t = 0; t < 4; t++) {
                const float4* wp = (const float4*)&wsm[(ci * 64 + co_g * 4 + t) * 16];
                float4 w0 = wp[0], w1 = wp[1], w2 = wp[2], w3 = wp[3];
                float wv[16] = {w0.x, w0.y, w0.z, w0.w, w1.x, w1.y, w1.z, w1.w,
                                w2.x, w2.y, w2.z, w2.w, w3.x, w3.y, w3.z, w3.w};
#pragma unroll
                for (int qy = 0; qy < 2; qy++)
#pragma unroll
                    for (int qx = 0; qx < 2; qx++)
#pragma unroll
                        for (int ry = 0; ry < 2; ry++)
#pragma unroll
                            for (int rx = 0; rx < 2; rx++) {
                                float s = acc[t * 16 + qy * 8 + qx * 4 + ry * 2 + rx];
#pragma unroll
                                for (int dy = 0; dy < 2; dy++)
#pragma unroll
                                    for (int dx = 0; dx < 2; dx++)
                                        s += wv[(2 * dy + ry) * 4 + (2 * dx + rx)] *
                                             iv[qy + dy + ry][qx + dx + rx];
                                acc[t * 16 + qy * 8 + qx * 4 + ry * 2 + rx] = s;
                            }
            }
        }
    }
    float* out_n = out + (size_t)n * COUT * HOUT * HOUT;
#pragma unroll
    for (int t = 0; t < 4; t++) {
        int co = co_blk * 64 + co_g * 4 + t;
#pragma unroll
        for (int qy = 0; qy < 2; qy++)
#pragma unroll
            for (int qx = 0; qx < 2; qx++)
#pragma unroll
                for (int ry = 0; ry < 2; ry++)
#pragma unroll
                    for (int rx = 0; rx < 2; rx++) {
                        int yo = 2 * (tqy + qy0 + qy) + ry;
                        int xo = 2 * (tqx + qx0 + qx) + rx;
                        float val = acc[t * 16 + qy * 8 + qx * 4 + ry * 2 + rx];
                        if (RELU) val = fmaxf(val, 0.f);
                        out_n[co * HOUT * HOUT + yo * HOUT + xo] = val;
                    }
    }
}

// ---------------- deconv3: 64 -> 3 channels, 32 -> 64, writes d_out (no relu) -------------
__global__ __launch_bounds__(256) void deconv3_kernel(const float* __restrict__ in,
                                                      const float* __restrict__ wgt,
                                                      float* __restrict__ out) {
    int n = blockIdx.x;
    __shared__ float sin_[4 * 34 * 34];   // 4 ci x padded 34x34
    __shared__ float wsm[3 * 64 * 16];    // [(ci*3+co)*16 + tap]
    int tid = threadIdx.x;

    for (int idx = tid; idx < 3072; idx += 256) {
        int tap = idx & 15;
        int cc = idx >> 4;
        int co = cc % 3, ci = cc / 3;
        wsm[idx] = wgt[(co * 64 + ci) * 16 + tap];
    }

    int qy0 = (tid >> 4) * 2;
    int qx0 = (tid & 15) * 2;
    float acc[48];
#pragma unroll
    for (int i = 0; i < 48; i++) acc[i] = 0.f;

    const float* in_n = in + (size_t)n * 64 * 1024;
    for (int ci0 = 0; ci0 < 64; ci0 += 4) {
        __syncthreads();
        for (int idx = tid; idx < 4 * 1156; idx += 256) {
            int ci = idx / 1156, rem = idx % 1156;
            int py = rem / 34, px = rem % 34;
            int y = py - 1, x = px - 1;
            float v = 0.f;
            if (y >= 0 && y < 32 && x >= 0 && x < 32)
                v = in_n[(ci0 + ci) * 1024 + y * 32 + x];
            sin_[idx] = v;
        }
        __syncthreads();
#pragma unroll 1
        for (int ci = 0; ci < 4; ci++) {
            float iv[4][4];
#pragma unroll
            for (int yy = 0; yy < 4; yy++)
#pragma unroll
                for (int xx = 0; xx < 4; xx++)
                    iv[yy][xx] = sin_[ci * 1156 + (qy0 + yy) * 34 + (qx0 + xx)];
#pragma unroll
            for (int co = 0; co < 3; co++) {
                const float4* wp = (const float4*)&wsm[((ci0 + ci) * 3 + co) * 16];
                float4 w0 = wp[0], w1 = wp[1], w2 = wp[2], w3 = wp[3];
                float wv[16] = {w0.x, w0.y, w0.z, w0.w, w1.x, w1.y, w1.z, w1.w,
                                w2.x, w2.y, w2.z, w2.w, w3.x, w3.y, w3.z, w3.w};
#pragma unroll
                for (int qy = 0; qy < 2; qy++)
#pragma unroll
                    for (int qx = 0; qx < 2; qx++)
#pragma unroll
                        for (int ry = 0; ry < 2; ry++)
#pragma unroll
                            for (int rx = 0; rx < 2; rx++) {
                                float s = acc[co * 16 + qy * 8 + qx * 4 + ry * 2 + rx];
#pragma unroll
                                for (int dy = 0; dy < 2; dy++)
#pragma unroll
                                    for (int dx = 0; dx < 2; dx++)
                                        s += wv[(2 * dy + ry) * 4 + (2 * dx + rx)] *
                                             iv[qy + dy + ry][qx + dx + rx];
                                acc[co * 16 + qy * 8 + qx * 4 + ry * 2 + rx] = s;
                            }
            }
        }
    }
    float* out_n = out + (size_t)n * 3 * 4096;
#pragma unroll
    for (int co = 0; co < 3; co++)
#pragma unroll
        for (int qy = 0; qy < 2; qy++)
#pragma unroll
            for (int qx = 0; qx < 2; qx++)
#pragma unroll
                for (int ry = 0; ry < 2; ry++)
#pragma unroll
                    for (int rx = 0; rx < 2; rx++) {
                        int yo = 2 * (qy0 + qy) + ry;
                        int xo = 2 * (qx0 + qx) + rx;
                        out_n[co * 4096 + yo * 64 + xo] =
                            acc[co * 16 + qy * 8 + qx * 4 + ry * 2 + rx];
                    }
}

// -----------------------------------------------------------------------------------------
extern "C" void kernel_launch(void* const* d_in, const int* in_sizes, int n_in,
                              void* d_out, int out_size) {
    (void)in_sizes; (void)n_in; (void)out_size;
    const float* angles   = (const float*)d_in[0];
    const float* item_rep = (const float*)d_in[1];
    const float* w0       = (const float*)d_in[2];
    const float* b0       = (const float*)d_in[3];
    const float* w1       = (const float*)d_in[4];
    const float* w2       = (const float*)d_in[5];
    const float* w3       = (const float*)d_in[6];
    float* out = (float*)d_out;

    float *p_item, *p_h0, *p_h1, *p_h2;
    cudaGetSymbolAddress((void**)&p_item, g_item);
    cudaGetSymbolAddress((void**)&p_h0, g_h0);
    cudaGetSymbolAddress((void**)&p_h1, g_h1);
    cudaGetSymbolAddress((void**)&p_h2, g_h2);

    init_jd_kernel<<<1, 288>>>();
    wigner_kernel<<<(N_SAMP * REP + 127) / 128, 128>>>(angles, item_rep);
    dense_kernel<<<dim3(DENSE_N / 64, N_SAMP / 64), 256>>>(p_item, w0, b0, p_h0);
    deconv_kernel<256, 128, 8, true><<<dim3(N_SAMP, 2, 1), 256>>>(p_h0, w1, p_h1);
    deconv_kernel<128, 64, 16, true><<<dim3(N_SAMP, 1, 4), 256>>>(p_h1, w2, p_h2);
    deconv3_kernel<<<N_SAMP, 256>>>(p_h2, w3, out);
}

// round 2
// speedup vs baseline: 1.1328x; 1.1328x over previous
#include <cuda_runtime.h>
#include <math.h>
#include <stdint.h>

#define N_SAMP 2048
#define MDIMS  36
#define REP    10
#define FEAT   360           // 36*10
#define DENSE_N 16384        // 256*8*8

typedef unsigned long long u64;

// ---------------- packed f32x2 helpers (Blackwell FFMA2 path) ----------------
__device__ __forceinline__ u64 fma2(u64 a, u64 b, u64 c) {
    u64 d;
    asm("fma.rn.f32x2 %0, %1, %2, %3;" : "=l"(d) : "l"(a), "l"(b), "l"(c));
    return d;
}
__device__ __forceinline__ u64 bcast2(float x) {
    u64 r; unsigned xi = __float_as_uint(x);
    asm("mov.b64 %0, {%1, %2};" : "=l"(r) : "r"(xi), "r"(xi));
    return r;
}
__device__ __forceinline__ u64 pack2(float lo, float hi) {
    u64 r; unsigned a = __float_as_uint(lo), b = __float_as_uint(hi);
    asm("mov.b64 %0, {%1, %2};" : "=l"(r) : "r"(a), "r"(b));
    return r;
}
__device__ __forceinline__ float2 unpk2(u64 p) {
    unsigned lo, hi;
    asm("mov.b64 {%0, %1}, %2;" : "=r"(lo), "=r"(hi) : "l"(p));
    return make_float2(__uint_as_float(lo), __uint_as_float(hi));
}

// ---------------- scratch (static device globals; no runtime alloc) ----------
__device__ float g_JD[286];
__device__ float g_item[N_SAMP * FEAT];
__device__ float g_h0[N_SAMP * 16384];
__device__ float g_h1[N_SAMP * 128 * 256];
__device__ float g_h2[N_SAMP * 64 * 1024];

__device__ __constant__ int c_off[7] = {0, 1, 10, 35, 84, 165, 286};

// ---------------- J_l = Re(C d^l(pi/2) C^H) computed on device ---------------
__device__ double dfact(int n) { double r = 1.0; for (int i = 2; i <= n; i++) r *= (double)i; return r; }

__device__ double small_d(int l, int mp, int m) {
    const double ch = 0.70710678118654752440;
    const double sh = 0.70710678118654752440;
    double pref = sqrt(dfact(l + mp) * dfact(l - mp) * dfact(l + m) * dfact(l - m));
    int smin = max(0, m - mp);
    int smax = min(l + m, l - mp);
    double tot = 0.0;
    for (int s = smin; s <= smax; s++) {
        double sign = ((mp - m + s) & 1) ? -1.0 : 1.0;
        double denom = dfact(l + m - s) * dfact(s) * dfact(mp - m + s) * dfact(l - mp - s);
        tot += sign / denom * pow(ch, (double)(2 * l + m - mp - 2 * s)) * pow(sh, (double)(mp - m + 2 * s));
    }
    return pref * tot;
}

__device__ void c2r_row(int l, int i, int* col, double* re, double* im, int* cnt) {
    int m = i - l;
    const double s = 0.70710678118654752440;
    if (m < 0) {
        double sgn = (m & 1) ? -1.0 : 1.0;
        col[0] = l + m; re[0] = 0.0; im[0] = s;
        col[1] = l - m; re[1] = 0.0; im[1] = -sgn * s;
        *cnt = 2;
    } else if (m == 0) {
        col[0] = l; re[0] = 1.0; im[0] = 0.0; *cnt = 1;
    } else {
        double sgn = (m & 1) ? -1.0 : 1.0;
        col[0] = l - m; re[0] = s;        im[0] = 0.0;
        col[1] = l + m; re[1] = sgn * s;  im[1] = 0.0;
        *cnt = 2;
    }
}

__global__ void init_jd_kernel() {
    int idx = threadIdx.x;
    if (idx >= 286) return;
    int l = 0;
    while (idx >= c_off[l + 1]) l++;
    int e = idx - c_off[l];
    int sz = 2 * l + 1;
    int i = e / sz, j = e % sz;
    int ca_c[2], cb_c[2], na, nb;
    double ca_re[2], ca_im[2], cb_re[2], cb_im[2];
    c2r_row(l, i, ca_c, ca_re, ca_im, &na);
    c2r_row(l, j, cb_c, cb_re, cb_im, &nb);
    double acc = 0.0;
    for (int a = 0; a < na; a++)
        for (int b = 0; b < nb; b++) {
            double cross = ca_re[a] * cb_re[b] + ca_im[a] * cb_im[b];
            if (cross != 0.0)
                acc += cross * small_d(l, ca_c[a] - l, cb_c[b] - l);
        }
    g_JD[idx] = (float)acc;
}

// ---------------- Wigner apply ------------------------------------------------
__device__ __forceinline__ void zrot_apply(const float* v, int sz, int l, float ang, float* out) {
    for (int i = 0; i < sz; i++) {
        float f = (float)(l - i);
        float s, c;
        sincosf(f * ang, &s, &c);
        out[i] = c * v[i] + s * v[sz - 1 - i];
    }
}

__global__ void wigner_kernel(const float* __restrict__ angles, const float* __restrict__ item_rep) {
    int t = blockIdx.x * blockDim.x + threadIdx.x;
    if (t >= N_SAMP * REP) return;
    int n = t / REP, r = t % REP;
    float a0 = angles[n * 3 + 0];
    float a1 = angles[n * 3 + 1];
    float a2 = angles[n * 3 + 2];
    float v[11], w[11];
    for (int l = 0; l <= 5; l++) {
        int sz = 2 * l + 1;
        const float* J = &g_JD[c_off[l]];
        for (int i = 0; i < sz; i++) v[i] = item_rep[(l * l + i) * REP + r];
        zrot_apply(v, sz, l, a2, w);
        for (int i = 0; i < sz; i++) {
            float s = 0.f;
            for (int j = 0; j < sz; j++) s += J[i * sz + j] * w[j];
            v[i] = s;
        }
        zrot_apply(v, sz, l, a1, w);
        for (int i = 0; i < sz; i++) {
            float s = 0.f;
            for (int j = 0; j < sz; j++) s += J[i * sz + j] * w[j];
            v[i] = s;
        }
        zrot_apply(v, sz, l, a0, w);
        for (int i = 0; i < sz; i++)
            g_item[n * FEAT + (l * l + i) * REP + r] = w[i];
    }
}

// ---------------- dense: h0 = relu(item @ w0 + b0) ----------------------------
__global__ __launch_bounds__(256) void dense_kernel(const float* __restrict__ A,
                                                    const float* __restrict__ B,
                                                    const float* __restrict__ bias,
                                                    float* __restrict__ C) {
    __shared__ float As[8][68];
    __shared__ float Bs[8][64];
    int tid = threadIdx.x;
    int bn = blockIdx.x, bm = blockIdx.y;
    int tx = tid & 15, ty = tid >> 4;
    u64 accp[4][2];
#pragma unroll
    for (int i = 0; i < 4; i++) { accp[i][0] = 0ull; accp[i][1] = 0ull; }

    int ka = tid & 7, ma = tid >> 3;
    int kb = tid >> 6, nb = tid & 63;
    const float* Ab = A + (size_t)(bm * 64) * FEAT;
    const float* Bb = B + bn * 64;

    for (int k0 = 0; k0 < FEAT; k0 += 8) {
        __syncthreads();
        As[ka][ma]      = Ab[(size_t)ma * FEAT + k0 + ka];
        As[ka][ma + 32] = Ab[(size_t)(ma + 32) * FEAT + k0 + ka];
        Bs[kb][nb]      = Bb[(size_t)(k0 + kb) * DENSE_N + nb];
        Bs[kb + 4][nb]  = Bb[(size_t)(k0 + kb + 4) * DENSE_N + nb];
        __syncthreads();
#pragma unroll
        for (int k = 0; k < 8; k++) {
            float4 a4 = *(const float4*)&As[k][ty * 4];
            ulonglong2 b2 = *(const ulonglong2*)&Bs[k][tx * 4];
            u64 ab[4] = {bcast2(a4.x), bcast2(a4.y), bcast2(a4.z), bcast2(a4.w)};
#pragma unroll
            for (int i = 0; i < 4; i++) {
                accp[i][0] = fma2(ab[i], b2.x, accp[i][0]);
                accp[i][1] = fma2(ab[i], b2.y, accp[i][1]);
            }
        }
    }
    float4 bi4 = *(const float4*)&bias[bn * 64 + tx * 4];
    float bv[4] = {bi4.x, bi4.y, bi4.z, bi4.w};
#pragma unroll
    for (int i = 0; i < 4; i++) {
        int m = bm * 64 + ty * 4 + i;
        float2 p0 = unpk2(accp[i][0]);
        float2 p1 = unpk2(accp[i][1]);
        float4 o;
        o.x = fmaxf(p0.x + bv[0], 0.f);
        o.y = fmaxf(p0.y + bv[1], 0.f);
        o.z = fmaxf(p1.x + bv[2], 0.f);
        o.w = fmaxf(p1.y + bv[3], 0.f);
        *(float4*)&C[(size_t)m * DENSE_N + bn * 64 + tx * 4] = o;
    }
}

// ---------------- transposed conv (k=4, s=2, SAME) via parity decomposition ----
// Packed over output-channel pairs: weight smem layout [ci][tap][co].
template <int CIN, int COUT, int HIN, bool RELU>
__global__ __launch_bounds__(256, 2) void deconv_kernel(const float* __restrict__ in,
                                                        const float* __restrict__ wgt,
                                                        float* __restrict__ out) {
    const int HOUT = HIN * 2;
    const int TILES_X = HIN / 8;
    int n = blockIdx.x;
    int co_blk = blockIdx.y;
    int tile = blockIdx.z;
    int tqy = (tile / TILES_X) * 8;
    int tqx = (tile % TILES_X) * 8;

    __shared__ float sin_[8 * 100];        // 8 ci x padded 10x10 input tile
    __shared__ float wsm[8 * 16 * 64];     // [ci][tap][co]

    int tid = threadIdx.x;
    int co_g = tid >> 4;                   // 0..15 -> 4 co each (2 packed pairs)
    int q_g = tid & 15;
    int qy0 = (q_g >> 2) * 2;
    int qx0 = (q_g & 3) * 2;

    u64 accp[2][16];
#pragma unroll
    for (int p = 0; p < 2; p++)
#pragma unroll
        for (int i = 0; i < 16; i++) accp[p][i] = 0ull;

    const float* in_n = in + (size_t)n * CIN * HIN * HIN;
    const float4* wg4 = (const float4*)wgt;

    for (int ci0 = 0; ci0 < CIN; ci0 += 8) {
        __syncthreads();
        // input tile (zero-padded halo)
        for (int idx = tid; idx < 800; idx += 256) {
            int ci = idx / 100, rem = idx % 100;
            int py = rem / 10, px = rem % 10;
            int y = tqy + py - 1, x = tqx + px - 1;
            float val = 0.f;
            if (y >= 0 && y < HIN && x >= 0 && x < HIN)
                val = in_n[(ci0 + ci) * HIN * HIN + y * HIN + x];
            sin_[idx] = val;
        }
        // weights: relayout to [ci][tap][co]
        for (int idx = tid; idx < 2048; idx += 256) {
            int ci = idx >> 8;
            int rr = idx & 255;
            int co = rr >> 2;
            int t4 = rr & 3;
            float4 w = wg4[((size_t)(co_blk * 64 + co) * CIN + ci0 + ci) * 4 + t4];
            wsm[(ci * 16 + t4 * 4 + 0) * 64 + co] = w.x;
            wsm[(ci * 16 + t4 * 4 + 1) * 64 + co] = w.y;
            wsm[(ci * 16 + t4 * 4 + 2) * 64 + co] = w.z;
            wsm[(ci * 16 + t4 * 4 + 3) * 64 + co] = w.w;
        }
        __syncthreads();
#pragma unroll 1
        for (int ci = 0; ci < 8; ci++) {
            u64 ivp[4][4];
#pragma unroll
            for (int yy = 0; yy < 4; yy++)
#pragma unroll
                for (int xx = 0; xx < 4; xx++)
                    ivp[yy][xx] = bcast2(sin_[ci * 100 + (qy0 + yy) * 10 + (qx0 + xx)]);
#pragma unroll
            for (int tap = 0; tap < 16; tap++) {
                const int ky = tap >> 2, kx = tap & 3;
                const int ry = ky & 1, dy = ky >> 1;
                const int rx = kx & 1, dx = kx >> 1;
                ulonglong2 wv2 = *(const ulonglong2*)&wsm[(ci * 16 + tap) * 64 + co_g * 4];
#pragma unroll
                for (int qy = 0; qy < 2; qy++)
#pragma unroll
                    for (int qx = 0; qx < 2; qx++) {
                        const int o = qy * 8 + qx * 4 + ry * 2 + rx;
                        u64 ivb = ivp[qy + dy + ry][qx + dx + rx];
                        accp[0][o] = fma2(wv2.x, ivb, accp[0][o]);
                        accp[1][o] = fma2(wv2.y, ivb, accp[1][o]);
                    }
            }
        }
    }
    float* out_n = out + (size_t)n * COUT * HOUT * HOUT;
#pragma unroll
    for (int p = 0; p < 2; p++)
#pragma unroll
        for (int qy = 0; qy < 2; qy++)
#pragma unroll
            for (int qx = 0; qx < 2; qx++)
#pragma unroll
                for (int ry = 0; ry < 2; ry++)
#pragma unroll
                    for (int rx = 0; rx < 2; rx++) {
                        int o = qy * 8 + qx * 4 + ry * 2 + rx;
                        float2 v = unpk2(accp[p][o]);
                        int yo = 2 * (tqy + qy0 + qy) + ry;
                        int xo = 2 * (tqx + qx0 + qx) + rx;
                        int co = co_blk * 64 + co_g * 4 + p * 2;
                        float v0 = RELU ? fmaxf(v.x, 0.f) : v.x;
                        float v1 = RELU ? fmaxf(v.y, 0.f) : v.y;
                        out_n[(co + 0) * HOUT * HOUT + yo * HOUT + xo] = v0;
                        out_n[(co + 1) * HOUT * HOUT + yo * HOUT + xo] = v1;
                    }
}

// ---------------- deconv3: 64 -> 3 channels, 32 -> 64 (packed over qx) ---------
__global__ __launch_bounds__(256) void deconv3_kernel(const float* __restrict__ in,
                                                      const float* __restrict__ wgt,
                                                      float* __restrict__ out) {
    int n = blockIdx.x;
    __shared__ float sin_[4 * 34 * 34];        // 4 ci x padded 34x34
    __shared__ float wsm[3 * 64 * 16 * 2];     // broadcast pairs {w,w}
    int tid = threadIdx.x;

    for (int idx = tid; idx < 3072; idx += 256) {
        int tap = idx & 15;
        int cc = idx >> 4;
        int co = cc % 3, ci = cc / 3;
        float w = wgt[(co * 64 + ci) * 16 + tap];
        wsm[((ci * 3 + co) * 16 + tap) * 2 + 0] = w;
        wsm[((ci * 3 + co) * 16 + tap) * 2 + 1] = w;
    }

    int qy0 = (tid >> 4) * 2;
    int qx0 = (tid & 15) * 2;
    u64 accp[3][8];
#pragma unroll
    for (int c = 0; c < 3; c++)
#pragma unroll
        for (int i = 0; i < 8; i++) accp[c][i] = 0ull;

    const float* in_n = in + (size_t)n * 64 * 1024;
    for (int ci0 = 0; ci0 < 64; ci0 += 4) {
        __syncthreads();
        for (int idx = tid; idx < 4 * 1156; idx += 256) {
            int ci = idx / 1156, rem = idx % 1156;
            int py = rem / 34, px = rem % 34;
            int y = py - 1, x = px - 1;
            float v = 0.f;
            if (y >= 0 && y < 32 && x >= 0 && x < 32)
                v = in_n[(ci0 + ci) * 1024 + y * 32 + x];
            sin_[idx] = v;
        }
        __syncthreads();
#pragma unroll 1
        for (int ci = 0; ci < 4; ci++) {
            float iv[4][4];
#pragma unroll
            for (int yy = 0; yy < 4; yy++)
#pragma unroll
                for (int xx = 0; xx < 4; xx++)
                    iv[yy][xx] = sin_[ci * 1156 + (qy0 + yy) * 34 + (qx0 + xx)];
            u64 ivp2[4][3];
#pragma unroll
            for (int yy = 0; yy < 4; yy++)
#pragma unroll
                for (int xx = 0; xx < 3; xx++)
                    ivp2[yy][xx] = pack2(iv[yy][xx], iv[yy][xx + 1]);
#pragma unroll
            for (int co = 0; co < 3; co++) {
#pragma unroll
                for (int tap = 0; tap < 16; tap++) {
                    const int ky = tap >> 2, kx = tap & 3;
                    const int ry = ky & 1, dy = ky >> 1;
                    const int rx = kx & 1, dx = kx >> 1;
                    u64 wp = *(const u64*)&wsm[(((ci0 + ci) * 3 + co) * 16 + tap) * 2];
#pragma unroll
                    for (int qy = 0; qy < 2; qy++) {
                        const int o = qy * 4 + ry * 2 + rx;
                        accp[co][o] = fma2(wp, ivp2[qy + dy + ry][dx + rx], accp[co][o]);
                    }
                }
            }
        }
    }
    float* out_n = out + (size_t)n * 3 * 4096;
#pragma unroll
    for (int co = 0; co < 3; co++)
#pragma unroll
        for (int qy = 0; qy < 2; qy++)
#pragma unroll
            for (int ry = 0; ry < 2; ry++)
#pragma unroll
                for (int rx = 0; rx < 2; rx++) {
                    float2 v = unpk2(accp[co][qy * 4 + ry * 2 + rx]);
                    int yo = 2 * (qy0 + qy) + ry;
                    int xo0 = 2 * (qx0 + 0) + rx;
                    int xo1 = 2 * (qx0 + 1) + rx;
                    out_n[co * 4096 + yo * 64 + xo0] = v.x;
                    out_n[co * 4096 + yo * 64 + xo1] = v.y;
                }
}

// -----------------------------------------------------------------------------------------
extern "C" void kernel_launch(void* const* d_in, const int* in_sizes, int n_in,
                              void* d_out, int out_size) {
    (void)in_sizes; (void)n_in; (void)out_size;
    const float* angles   = (const float*)d_in[0];
    const float* item_rep = (const float*)d_in[1];
    const float* w0       = (const float*)d_in[2];
    const float* b0       = (const float*)d_in[3];
    const float* w1       = (const float*)d_in[4];
    const float* w2       = (const float*)d_in[5];
    const float* w3       = (const float*)d_in[6];
    float* out = (float*)d_out;

    float *p_item, *p_h0, *p_h1, *p_h2;
    cudaGetSymbolAddress((void**)&p_item, g_item);
    cudaGetSymbolAddress((void**)&p_h0, g_h0);
    cudaGetSymbolAddress((void**)&p_h1, g_h1);
    cudaGetSymbolAddress((void**)&p_h2, g_h2);

    init_jd_kernel<<<1, 288>>>();
    wigner_kernel<<<(N_SAMP * REP + 127) / 128, 128>>>(angles, item_rep);
    dense_kernel<<<dim3(DENSE_N / 64, N_SAMP / 64), 256>>>(p_item, w0, b0, p_h0);
    deconv_kernel<256, 128, 8, true><<<dim3(N_SAMP, 2, 1), 256>>>(p_h0, w1, p_h1);
    deconv_kernel<128, 64, 16, true><<<dim3(N_SAMP, 1, 4), 256>>>(p_h1, w2, p_h2);
    deconv3_kernel<<<N_SAMP, 256>>>(p_h2, w3, out);
}

// round 4
// speedup vs baseline: 1.9584x; 1.7288x over previous
#include <cuda_runtime.h>
#include <cuda_bf16.h>
#include <math.h>
#include <stdint.h>

typedef unsigned int u32;
typedef unsigned long long u64;

#define N_SAMP 2048
#define MDIMS  36
#define REP    10
#define FEAT   360
#define DENSE_N 16384        // 256*8*8

// ---------------- packed f32x2 helpers ----------------
__device__ __forceinline__ u64 fma2(u64 a, u64 b, u64 c) {
    u64 d;
    asm("fma.rn.f32x2 %0, %1, %2, %3;" : "=l"(d) : "l"(a), "l"(b), "l"(c));
    return d;
}
__device__ __forceinline__ u64 bcast2(float x) {
    u64 r; unsigned xi = __float_as_uint(x);
    asm("mov.b64 %0, {%1, %2};" : "=l"(r) : "r"(xi), "r"(xi));
    return r;
}
__device__ __forceinline__ u64 pack2(float lo, float hi) {
    u64 r; unsigned a = __float_as_uint(lo), b = __float_as_uint(hi);
    asm("mov.b64 %0, {%1, %2};" : "=l"(r) : "r"(a), "r"(b));
    return r;
}
__device__ __forceinline__ float2 unpk2(u64 p) {
    unsigned lo, hi;
    asm("mov.b64 {%0, %1}, %2;" : "=r"(lo), "=r"(hi) : "l"(p));
    return make_float2(__uint_as_float(lo), __uint_as_float(hi));
}

// ---------------- bf16 pack/unpack ----------------
__device__ __forceinline__ u32 bf16pack(float lo, float hi) {
    u32 r;
    asm("cvt.rn.satfinite.bf16x2.f32 %0, %1, %2;" : "=r"(r) : "f"(hi), "f"(lo));
    return r;
}
__device__ __forceinline__ float2 bf16unpk(u32 u) {
    __nv_bfloat162 h = *reinterpret_cast<__nv_bfloat162*>(&u);
    return __bfloat1622float2(h);
}

// ---------------- warp MMA helpers (HMMA path, plain compute_103 PTX) --------
__device__ __forceinline__ u32 smem_to_u32(const void* p) {
    u32 a;
    asm("{ .reg .u64 t; cvta.to.shared.u64 t, %1; cvt.u32.u64 %0, t; }" : "=r"(a) : "l"(p));
    return a;
}
__device__ __forceinline__ void ldsm4(u32* r, u32 addr) {
    asm volatile("ldmatrix.sync.aligned.m8n8.x4.shared.b16 {%0,%1,%2,%3}, [%4];"
                 : "=r"(r[0]), "=r"(r[1]), "=r"(r[2]), "=r"(r[3]) : "r"(addr));
}
__device__ __forceinline__ void mma16816(float* d, const u32* a, u32 b0, u32 b1) {
    asm volatile(
        "mma.sync.aligned.m16n8k16.row.col.f32.bf16.bf16.f32 "
        "{%0,%1,%2,%3}, {%4,%5,%6,%7}, {%8,%9}, {%0,%1,%2,%3};"
        : "+f"(d[0]), "+f"(d[1]), "+f"(d[2]), "+f"(d[3])
        : "r"(a[0]), "r"(a[1]), "r"(a[2]), "r"(a[3]), "r"(b0), "r"(b1));
}

// ---------------- scratch ----------------
__device__ float g_JD[286];
__device__ float g_item[N_SAMP * FEAT];
__device__ __align__(16) __nv_bfloat16 g_h0hi[N_SAMP * 16384];      // NHWC [n,8,8,256]
__device__ __align__(16) __nv_bfloat16 g_h0lo[N_SAMP * 16384];
__device__ __align__(16) __nv_bfloat16 g_h1hi[N_SAMP * 256 * 128];  // NHWC [n,16,16,128]
__device__ __align__(16) __nv_bfloat16 g_h1lo[N_SAMP * 256 * 128];
__device__ __align__(16) float g_h2[N_SAMP * 1024 * 64];            // NHWC [n,32,32,64] fp32
__device__ __align__(16) __nv_bfloat16 g_w1hi[4 * 128 * 1024];
__device__ __align__(16) __nv_bfloat16 g_w1lo[4 * 128 * 1024];
__device__ __align__(16) __nv_bfloat16 g_w2hi[4 * 64 * 512];
__device__ __align__(16) __nv_bfloat16 g_w2lo[4 * 64 * 512];

__device__ __constant__ int c_off[7] = {0, 1, 10, 35, 84, 165, 286};

// ---------------- J_l init ----------------
__device__ double dfact(int n) { double r = 1.0; for (int i = 2; i <= n; i++) r *= (double)i; return r; }

__device__ double small_d(int l, int mp, int m) {
    const double ch = 0.70710678118654752440, sh = 0.70710678118654752440;
    double pref = sqrt(dfact(l + mp) * dfact(l - mp) * dfact(l + m) * dfact(l - m));
    int smin = max(0, m - mp), smax = min(l + m, l - mp);
    double tot = 0.0;
    for (int s = smin; s <= smax; s++) {
        double sign = ((mp - m + s) & 1) ? -1.0 : 1.0;
        double denom = dfact(l + m - s) * dfact(s) * dfact(mp - m + s) * dfact(l - mp - s);
        tot += sign / denom * pow(ch, (double)(2 * l + m - mp - 2 * s)) * pow(sh, (double)(mp - m + 2 * s));
    }
    return pref * tot;
}

__device__ void c2r_row(int l, int i, int* col, double* re, double* im, int* cnt) {
    int m = i - l;
    const double s = 0.70710678118654752440;
    if (m < 0) {
        double sgn = (m & 1) ? -1.0 : 1.0;
        col[0] = l + m; re[0] = 0.0; im[0] = s;
        col[1] = l - m; re[1] = 0.0; im[1] = -sgn * s;
        *cnt = 2;
    } else if (m == 0) {
        col[0] = l; re[0] = 1.0; im[0] = 0.0; *cnt = 1;
    } else {
        double sgn = (m & 1) ? -1.0 : 1.0;
        col[0] = l - m; re[0] = s;        im[0] = 0.0;
        col[1] = l + m; re[1] = sgn * s;  im[1] = 0.0;
        *cnt = 2;
    }
}

__global__ void init_jd_kernel() {
    int idx = threadIdx.x;
    if (idx >= 286) return;
    int l = 0;
    while (idx >= c_off[l + 1]) l++;
    int e = idx - c_off[l];
    int sz = 2 * l + 1;
    int i = e / sz, j = e % sz;
    int ca_c[2], cb_c[2], na, nb;
    double ca_re[2], ca_im[2], cb_re[2], cb_im[2];
    c2r_row(l, i, ca_c, ca_re, ca_im, &na);
    c2r_row(l, j, cb_c, cb_re, cb_im, &nb);
    double acc = 0.0;
    for (int a = 0; a < na; a++)
        for (int b = 0; b < nb; b++) {
            double cross = ca_re[a] * cb_re[b] + ca_im[a] * cb_im[b];
            if (cross != 0.0) acc += cross * small_d(l, ca_c[a] - l, cb_c[b] - l);
        }
    g_JD[idx] = (float)acc;
}

// ---------------- Wigner ----------------
__device__ __forceinline__ void zrot_apply(const float* v, int sz, int l, float ang, float* out) {
    for (int i = 0; i < sz; i++) {
        float f = (float)(l - i);
        float s, c;
        sincosf(f * ang, &s, &c);
        out[i] = c * v[i] + s * v[sz - 1 - i];
    }
}

__global__ void wigner_kernel(const float* __restrict__ angles, const float* __restrict__ item_rep) {
    int t = blockIdx.x * blockDim.x + threadIdx.x;
    if (t >= N_SAMP * REP) return;
    int n = t / REP, r = t % REP;
    float a0 = angles[n * 3 + 0], a1 = angles[n * 3 + 1], a2 = angles[n * 3 + 2];
    float v[11], w[11];
    for (int l = 0; l <= 5; l++) {
        int sz = 2 * l + 1;
        const float* J = &g_JD[c_off[l]];
        for (int i = 0; i < sz; i++) v[i] = item_rep[(l * l + i) * REP + r];
        zrot_apply(v, sz, l, a2, w);
        for (int i = 0; i < sz; i++) { float s = 0.f; for (int j = 0; j < sz; j++) s += J[i * sz + j] * w[j]; v[i] = s; }
        zrot_apply(v, sz, l, a1, w);
        for (int i = 0; i < sz; i++) { float s = 0.f; for (int j = 0; j < sz; j++) s += J[i * sz + j] * w[j]; v[i] = s; }
        zrot_apply(v, sz, l, a0, w);
        for (int i = 0; i < sz; i++) g_item[n * FEAT + (l * l + i) * REP + r] = w[i];
    }
}

// ---------------- dense: relu(item@w0+b0) -> NHWC bf16 hi/lo ----------------
__global__ __launch_bounds__(256) void dense_kernel(const float* __restrict__ A,
                                                    const float* __restrict__ B,
                                                    const float* __restrict__ bias,
                                                    __nv_bfloat16* __restrict__ Chi,
                                                    __nv_bfloat16* __restrict__ Clo) {
    __shared__ float As[8][68];
    __shared__ float Bs[8][64];
    int tid = threadIdx.x;
    int bn = blockIdx.x, bm = blockIdx.y;
    int tx = tid & 15, ty = tid >> 4;
    u64 accp[4][2];
#pragma unroll
    for (int i = 0; i < 4; i++) { accp[i][0] = 0ull; accp[i][1] = 0ull; }

    int ka = tid & 7, ma = tid >> 3;
    int kb = tid >> 6, nb = tid & 63;
    const float* Ab = A + (size_t)(bm * 64) * FEAT;
    const float* Bb = B + bn * 64;

    for (int k0 = 0; k0 < FEAT; k0 += 8) {
        __syncthreads();
        As[ka][ma]      = Ab[(size_t)ma * FEAT + k0 + ka];
        As[ka][ma + 32] = Ab[(size_t)(ma + 32) * FEAT + k0 + ka];
        Bs[kb][nb]      = Bb[(size_t)(k0 + kb) * DENSE_N + nb];
        Bs[kb + 4][nb]  = Bb[(size_t)(k0 + kb + 4) * DENSE_N + nb];
        __syncthreads();
#pragma unroll
        for (int k = 0; k < 8; k++) {
            float4 a4 = *(const float4*)&As[k][ty * 4];
            ulonglong2 b2 = *(const ulonglong2*)&Bs[k][tx * 4];
            u64 ab[4] = {bcast2(a4.x), bcast2(a4.y), bcast2(a4.z), bcast2(a4.w)};
#pragma unroll
            for (int i = 0; i < 4; i++) {
                accp[i][0] = fma2(ab[i], b2.x, accp[i][0]);
                accp[i][1] = fma2(ab[i], b2.y, accp[i][1]);
            }
        }
    }
    float4 bi4 = *(const float4*)&bias[bn * 64 + tx * 4];
    float bv[4] = {bi4.x, bi4.y, bi4.z, bi4.w};
#pragma unroll
    for (int i = 0; i < 4; i++) {
        int m = bm * 64 + ty * 4 + i;
        float2 p0 = unpk2(accp[i][0]);
        float2 p1 = unpk2(accp[i][1]);
        float vals[4] = {fmaxf(p0.x + bv[0], 0.f), fmaxf(p0.y + bv[1], 0.f),
                         fmaxf(p1.x + bv[2], 0.f), fmaxf(p1.y + bv[3], 0.f)};
#pragma unroll
        for (int jj = 0; jj < 4; jj++) {
            int pix = tx * 4 + jj;
            size_t idx = ((size_t)m * 64 + pix) * 256 + bn;
            __nv_bfloat16 h = __float2bfloat16(vals[jj]);
            Chi[idx] = h;
            Clo[idx] = __float2bfloat16(vals[jj] - __bfloat162float(h));
        }
    }
}

// ---------------- weight repack + bf16 split: [parity][co][k=(tap,ci)] --------
__global__ void repack_w_kernel(const float* __restrict__ w, __nv_bfloat16* __restrict__ bhi,
                                __nv_bfloat16* __restrict__ blo, int COUT, int CIN) {
    int idx = blockIdx.x * 256 + threadIdx.x;
    int K = 4 * CIN;
    int total = 4 * COUT * K;
    if (idx >= total) return;
    int p = idx / (COUT * K);
    int r = idx % (COUT * K);
    int co = r / K;
    int k = r % K;
    int t = k / CIN, ci = k % CIN;
    int dy = t >> 1, dx = t & 1, ry = p >> 1, rx = p & 1;
    float v = w[((co * CIN + ci) * 4 + (2 * dy + ry)) * 4 + (2 * dx + rx)];
    __nv_bfloat16 h = __float2bfloat16(v);
    bhi[idx] = h;
    blo[idx] = __float2bfloat16(v - __bfloat162float(h));
}

// ---------------- HMMA implicit-GEMM deconv ----------------
// CTA tile: 128 pixel-rows x COUT. K-stages of 64 (tap-major). bf16x3 split.
// Warp grid 4(m) x 2(n): warp tile 32 x COUT/2.
template <int CIN, int COUT, int HIN, bool OUT_BF16>
__global__ __launch_bounds__(256) void deconv_mma_kernel(
    const __nv_bfloat16* __restrict__ in_hi, const __nv_bfloat16* __restrict__ in_lo,
    const __nv_bfloat16* __restrict__ w_hi,  const __nv_bfloat16* __restrict__ w_lo,
    __nv_bfloat16* __restrict__ out_hi, __nv_bfloat16* __restrict__ out_lo,
    float* __restrict__ out_f) {
    constexpr int NSTAGE = 4 * CIN / 64;
    constexpr int HOUT = 2 * HIN;
    constexpr int PIX = HIN * HIN;
    constexpr int SROW = 144;            // smem row stride in bytes (64 bf16 + 16B pad)
    constexpr int ABYTES = 128 * SROW;
    constexpr int BBYTES = COUT * SROW;
    constexpr int NF8 = COUT / 16;       // n8 fragments per warp
    constexpr int NG  = COUT / 32;       // n16 ldmatrix groups per warp

    extern __shared__ __align__(16) char smem[];
    char* sAhi = smem;
    char* sAlo = smem + ABYTES;
    char* sBhi = smem + 2 * ABYTES;
    char* sBlo = smem + 2 * ABYTES + BBYTES;
    const u32 uAhi = smem_to_u32(sAhi);
    const u32 uAlo = uAhi + ABYTES;
    const u32 uBhi = uAhi + 2 * ABYTES;
    const u32 uBlo = uBhi + BBYTES;

    const int tid = threadIdx.x;
    const int wid = tid >> 5;
    const int lid = tid & 31;
    const int wm = wid >> 1;             // 0..3
    const int wn = wid & 1;              // 0..1
    const int m0 = blockIdx.x * 128;
    const int par = blockIdx.y;
    const int ry = par >> 1, rx = par & 1;

    const int lrow = lid & 15;
    const int lcol = (lid >> 4) << 4;    // byte offset of k-half
    int aoff0 = (wm * 32 + lrow) * SROW + lcol;
    int aoff1 = aoff0 + 16 * SROW;
    int boff[NG];
#pragma unroll
    for (int g = 0; g < NG; g++) boff[g] = (wn * (COUT / 2) + g * 16 + lrow) * SROW + lcol;

    float acc[2][NF8][4];
#pragma unroll
    for (int t = 0; t < 2; t++)
#pragma unroll
        for (int f = 0; f < NF8; f++)
#pragma unroll
            for (int j = 0; j < 4; j++) acc[t][f][j] = 0.f;

    for (int s = 0; s < NSTAGE; s++) {
        const int t_tap = s / (CIN / 64);
        const int ci0   = (s % (CIN / 64)) * 64;
        const int dy = t_tap >> 1, dx = t_tap & 1;
        __syncthreads();
        // ---- A copy (halo-padded, pre-split bf16 in gmem) ----
        for (int idx = tid; idx < 1024; idx += 256) {
            int row = idx >> 3, u4 = idx & 7;
            int r = m0 + row;
            int n = r / PIX, q = r % PIX;
            int qy = q / HIN, qx = q % HIN;
            int y = qy + dy - 1 + ry;
            int x = qx + dx - 1 + rx;
            uint4 vh = make_uint4(0u, 0u, 0u, 0u), vl = vh;
            if (y >= 0 && y < HIN && x >= 0 && x < HIN) {
                size_t base = (((size_t)n * HIN + y) * HIN + x) * CIN + ci0 + u4 * 8;
                vh = *(const uint4*)&in_hi[base];
                vl = *(const uint4*)&in_lo[base];
            }
            *(uint4*)(sAhi + row * SROW + u4 * 16) = vh;
            *(uint4*)(sAlo + row * SROW + u4 * 16) = vl;
        }
        // ---- B copy ----
        for (int idx = tid; idx < COUT * 8; idx += 256) {
            int co = idx >> 3, u4 = idx & 7;
            size_t base = ((size_t)par * COUT + co) * (4 * CIN) + s * 64 + u4 * 8;
            *(uint4*)(sBhi + co * SROW + u4 * 16) = *(const uint4*)&w_hi[base];
            *(uint4*)(sBlo + co * SROW + u4 * 16) = *(const uint4*)&w_lo[base];
        }
        __syncthreads();
        // ---- MMA over 4 k16 steps, 3 split terms ----
#pragma unroll
        for (int ks = 0; ks < 4; ks++) {
            u32 ah[2][4], al[2][4];
            u32 bh[NG][4], bl[NG][4];
            ldsm4(ah[0], uAhi + aoff0 + ks * 32);
            ldsm4(ah[1], uAhi + aoff1 + ks * 32);
            ldsm4(al[0], uAlo + aoff0 + ks * 32);
            ldsm4(al[1], uAlo + aoff1 + ks * 32);
#pragma unroll
            for (int g = 0; g < NG; g++) {
                ldsm4(bh[g], uBhi + boff[g] + ks * 32);
                ldsm4(bl[g], uBlo + boff[g] + ks * 32);
            }
#pragma unroll
            for (int tm = 0; tm < 2; tm++)
#pragma unroll
                for (int g = 0; g < NG; g++)
#pragma unroll
                    for (int h = 0; h < 2; h++) {
                        const int f = g * 2 + h;
                        mma16816(acc[tm][f], ah[tm], bh[g][h], bh[g][h + 2]);  // hi*hi
                        mma16816(acc[tm][f], ah[tm], bl[g][h], bl[g][h + 2]);  // hi*lo
                        mma16816(acc[tm][f], al[tm], bh[g][h], bh[g][h + 2]);  // lo*hi
                    }
        }
    }

    // ---- epilogue: ReLU + NHWC store ----
#pragma unroll
    for (int tm = 0; tm < 2; tm++) {
        int r0 = m0 + wm * 32 + tm * 16 + (lid >> 2);
#pragma unroll
        for (int rr = 0; rr < 2; rr++) {
            int r = r0 + rr * 8;
            int n = r / PIX, q = r % PIX;
            int yo = 2 * (q / HIN) + ry;
            int xo = 2 * (q % HIN) + rx;
            size_t obase = (((size_t)n * HOUT + yo) * HOUT + xo) * COUT;
#pragma unroll
            for (int f = 0; f < NF8; f++) {
                int ch = wn * (COUT / 2) + f * 8 + (lid & 3) * 2;
                float v0 = fmaxf(acc[tm][f][rr * 2 + 0], 0.f);
                float v1 = fmaxf(acc[tm][f][rr * 2 + 1], 0.f);
                if (OUT_BF16) {
                    u32 hp = bf16pack(v0, v1);
                    float2 hf = bf16unpk(hp);
                    u32 lp = bf16pack(v0 - hf.x, v1 - hf.y);
                    *(u32*)&out_hi[obase + ch] = hp;
                    *(u32*)&out_lo[obase + ch] = lp;
                } else {
                    *(float2*)&out_f[obase + ch] = make_float2(v0, v1);
                }
            }
        }
    }
}

// ---------------- deconv3: 64 -> 3, NHWC fp32 input, NCHW output ----------------
__global__ __launch_bounds__(256) void deconv3_kernel(const float* __restrict__ in,
                                                      const float* __restrict__ wgt,
                                                      float* __restrict__ out) {
    int n = blockIdx.x;
    __shared__ float sin_[34 * 34 * 4];
    __shared__ float wsm[3 * 64 * 16 * 2];
    int tid = threadIdx.x;

    for (int idx = tid; idx < 3072; idx += 256) {
        int tap = idx & 15;
        int cc = idx >> 4;
        int co = cc % 3, ci = cc / 3;
        float w = wgt[(co * 64 + ci) * 16 + tap];
        wsm[((ci * 3 + co) * 16 + tap) * 2 + 0] = w;
        wsm[((ci * 3 + co) * 16 + tap) * 2 + 1] = w;
    }

    int qy0 = (tid >> 4) * 2;
    int qx0 = (tid & 15) * 2;
    u64 accp[3][8];
#pragma unroll
    for (int c = 0; c < 3; c++)
#pragma unroll
        for (int i = 0; i < 8; i++) accp[c][i] = 0ull;

    const float* in_n = in + (size_t)n * 1024 * 64;
    for (int ci0 = 0; ci0 < 64; ci0 += 4) {
        __syncthreads();
        for (int idx = tid; idx < 1156; idx += 256) {
            int py = idx / 34, px = idx % 34;
            int y = py - 1, x = px - 1;
            float4 v = make_float4(0.f, 0.f, 0.f, 0.f);
            if (y >= 0 && y < 32 && x >= 0 && x < 32)
                v = *(const float4*)&in_n[(y * 32 + x) * 64 + ci0];
            *(float4*)&sin_[idx * 4] = v;
        }
        __syncthreads();
#pragma unroll 1
        for (int ci = 0; ci < 4; ci++) {
            float iv[4][4];
#pragma unroll
            for (int yy = 0; yy < 4; yy++)
#pragma unroll
                for (int xx = 0; xx < 4; xx++)
                    iv[yy][xx] = sin_[((qy0 + yy) * 34 + qx0 + xx) * 4 + ci];
            u64 ivp2[4][3];
#pragma unroll
            for (int yy = 0; yy < 4; yy++)
#pragma unroll
                for (int xx = 0; xx < 3; xx++)
                    ivp2[yy][xx] = pack2(iv[yy][xx], iv[yy][xx + 1]);
#pragma unroll
            for (int co = 0; co < 3; co++) {
#pragma unroll
                for (int tap = 0; tap < 16; tap++) {
                    const int ky = tap >> 2, kx = tap & 3;
                    const int ry = ky & 1, dy = ky >> 1;
                    const int rx = kx & 1, dx = kx >> 1;
                    u64 wp = *(const u64*)&wsm[(((ci0 + ci) * 3 + co) * 16 + tap) * 2];
#pragma unroll
                    for (int qy = 0; qy < 2; qy++) {
                        const int o = qy * 4 + ry * 2 + rx;
                        accp[co][o] = fma2(wp, ivp2[qy + dy + ry][dx + rx], accp[co][o]);
                    }
                }
            }
        }
    }
    float* out_n = out + (size_t)n * 3 * 4096;
#pragma unroll
    for (int co = 0; co < 3; co++)
#pragma unroll
        for (int qy = 0; qy < 2; qy++)
#pragma unroll
            for (int ry = 0; ry < 2; ry++)
#pragma unroll
                for (int rx = 0; rx < 2; rx++) {
                    float2 v = unpk2(accp[co][qy * 4 + ry * 2 + rx]);
                    int yo = 2 * (qy0 + qy) + ry;
                    int xo0 = 2 * (qx0 + 0) + rx;
                    int xo1 = 2 * (qx0 + 1) + rx;
                    out_n[co * 4096 + yo * 64 + xo0] = v.x;
                    out_n[co * 4096 + yo * 64 + xo1] = v.y;
                }
}

// -----------------------------------------------------------------------------------------
extern "C" void kernel_launch(void* const* d_in, const int* in_sizes, int n_in,
                              void* d_out, int out_size) {
    (void)in_sizes; (void)n_in; (void)out_size;
    const float* angles   = (const float*)d_in[0];
    const float* item_rep = (const float*)d_in[1];
    const float* w0       = (const float*)d_in[2];
    const float* b0       = (const float*)d_in[3];
    const float* w1       = (const float*)d_in[4];
    const float* w2       = (const float*)d_in[5];
    const float* w3       = (const float*)d_in[6];
    float* out = (float*)d_out;

    float *p_item, *p_h2;
    cudaGetSymbolAddress((void**)&p_item, g_item);
    cudaGetSymbolAddress((void**)&p_h2, g_h2);
    __nv_bfloat16 *p_h0hi, *p_h0lo, *p_h1hi, *p_h1lo;
    cudaGetSymbolAddress((void**)&p_h0hi, g_h0hi);
    cudaGetSymbolAddress((void**)&p_h0lo, g_h0lo);
    cudaGetSymbolAddress((void**)&p_h1hi, g_h1hi);
    cudaGetSymbolAddress((void**)&p_h1lo, g_h1lo);
    __nv_bfloat16 *p_w1hi, *p_w1lo, *p_w2hi, *p_w2lo;
    cudaGetSymbolAddress((void**)&p_w1hi, g_w1hi);
    cudaGetSymbolAddress((void**)&p_w1lo, g_w1lo);
    cudaGetSymbolAddress((void**)&p_w2hi, g_w2hi);
    cudaGetSymbolAddress((void**)&p_w2lo, g_w2lo);

    constexpr int SMEM1 = 2 * 128 * 144 + 2 * 128 * 144;  // A(hi,lo) + B(hi,lo) = 73728
    constexpr int SMEM2 = 2 * 128 * 144 + 2 * 64 * 144;   // 55296
    cudaFuncSetAttribute(deconv_mma_kernel<256, 128, 8, true>,
                         cudaFuncAttributeMaxDynamicSharedMemorySize, SMEM1);
    cudaFuncSetAttribute(deconv_mma_kernel<128, 64, 16, false>,
                         cudaFuncAttributeMaxDynamicSharedMemorySize, SMEM2);

    init_jd_kernel<<<1, 288>>>();
    repack_w_kernel<<<(4 * 128 * 1024) / 256, 256>>>(w1, p_w1hi, p_w1lo, 128, 256);
    repack_w_kernel<<<(4 * 64 * 512) / 256, 256>>>(w2, p_w2hi, p_w2lo, 64, 128);
    wigner_kernel<<<(N_SAMP * REP + 127) / 128, 128>>>(angles, item_rep);
    dense_kernel<<<dim3(DENSE_N / 64, N_SAMP / 64), 256>>>(p_item, w0, b0, p_h0hi, p_h0lo);
    deconv_mma_kernel<256, 128, 8, true><<<dim3(1024, 4), 256, SMEM1>>>(
        p_h0hi, p_h0lo, p_w1hi, p_w1lo, p_h1hi, p_h1lo, nullptr);
    deconv_mma_kernel<128, 64, 16, false><<<dim3(4096, 4), 256, SMEM2>>>(
        p_h1hi, p_h1lo, p_w2hi, p_w2lo, nullptr, nullptr, p_h2);
    deconv3_kernel<<<N_SAMP, 256>>>(p_h2, w3, out);
}

// round 5
// speedup vs baseline: 2.0176x; 1.0303x over previous
#include <cuda_runtime.h>
#include <cuda_bf16.h>
#include <math.h>
#include <stdint.h>

typedef unsigned int u32;
typedef unsigned long long u64;

#define N_SAMP 2048
#define MDIMS  36
#define REP    10
#define FEAT   360
#define DENSE_N 16384        // 256*8*8

// ---------------- packed f32x2 helpers ----------------
__device__ __forceinline__ u64 fma2(u64 a, u64 b, u64 c) {
    u64 d;
    asm("fma.rn.f32x2 %0, %1, %2, %3;" : "=l"(d) : "l"(a), "l"(b), "l"(c));
    return d;
}
__device__ __forceinline__ u64 bcast2(float x) {
    u64 r; unsigned xi = __float_as_uint(x);
    asm("mov.b64 %0, {%1, %2};" : "=l"(r) : "r"(xi), "r"(xi));
    return r;
}
__device__ __forceinline__ u64 pack2(float lo, float hi) {
    u64 r; unsigned a = __float_as_uint(lo), b = __float_as_uint(hi);
    asm("mov.b64 %0, {%1, %2};" : "=l"(r) : "r"(a), "r"(b));
    return r;
}
__device__ __forceinline__ float2 unpk2(u64 p) {
    unsigned lo, hi;
    asm("mov.b64 {%0, %1}, %2;" : "=r"(lo), "=r"(hi) : "l"(p));
    return make_float2(__uint_as_float(lo), __uint_as_float(hi));
}

// ---------------- bf16 pack/unpack ----------------
__device__ __forceinline__ u32 bf16pack(float lo, float hi) {
    u32 r;
    asm("cvt.rn.satfinite.bf16x2.f32 %0, %1, %2;" : "=r"(r) : "f"(hi), "f"(lo));
    return r;
}
__device__ __forceinline__ float2 bf16unpk(u32 u) {
    __nv_bfloat162 h = *reinterpret_cast<__nv_bfloat162*>(&u);
    return __bfloat1622float2(h);
}

// ---------------- warp MMA + cp.async helpers ----------------
__device__ __forceinline__ u32 smem_to_u32(const void* p) {
    u32 a;
    asm("{ .reg .u64 t; cvta.to.shared.u64 t, %1; cvt.u32.u64 %0, t; }" : "=r"(a) : "l"(p));
    return a;
}
__device__ __forceinline__ void ldsm4(u32* r, u32 addr) {
    asm volatile("ldmatrix.sync.aligned.m8n8.x4.shared.b16 {%0,%1,%2,%3}, [%4];"
                 : "=r"(r[0]), "=r"(r[1]), "=r"(r[2]), "=r"(r[3]) : "r"(addr));
}
__device__ __forceinline__ void mma16816(float* d, const u32* a, u32 b0, u32 b1) {
    asm volatile(
        "mma.sync.aligned.m16n8k16.row.col.f32.bf16.bf16.f32 "
        "{%0,%1,%2,%3}, {%4,%5,%6,%7}, {%8,%9}, {%0,%1,%2,%3};"
        : "+f"(d[0]), "+f"(d[1]), "+f"(d[2]), "+f"(d[3])
        : "r"(a[0]), "r"(a[1]), "r"(a[2]), "r"(a[3]), "r"(b0), "r"(b1));
}
__device__ __forceinline__ void cp16(u32 dst, const void* src, bool p) {
    asm volatile("cp.async.cg.shared.global [%0], [%1], 16, %2;"
                 :: "r"(dst), "l"(src), "r"(p ? 16 : 0) : "memory");
}
__device__ __forceinline__ void cp_commit() {
    asm volatile("cp.async.commit_group;" ::: "memory");
}
__device__ __forceinline__ void cp_wait1() {
    asm volatile("cp.async.wait_group 1;" ::: "memory");
}
__device__ __forceinline__ void cp_wait0() {
    asm volatile("cp.async.wait_group 0;" ::: "memory");
}

// ---------------- scratch ----------------
__device__ float g_JD[286];
__device__ float g_item[N_SAMP * FEAT];
__device__ __align__(16) __nv_bfloat16 g_h0hi[N_SAMP * 16384];      // NHWC [n,8,8,256]
__device__ __align__(16) __nv_bfloat16 g_h0lo[N_SAMP * 16384];
__device__ __align__(16) __nv_bfloat16 g_h1hi[N_SAMP * 256 * 128];  // NHWC [n,16,16,128]
__device__ __align__(16) __nv_bfloat16 g_h1lo[N_SAMP * 256 * 128];
__device__ __align__(16) float g_h2[N_SAMP * 1024 * 64];            // NHWC [n,32,32,64] fp32
__device__ __align__(16) __nv_bfloat16 g_w1hi[4 * 128 * 1024];
__device__ __align__(16) __nv_bfloat16 g_w1lo[4 * 128 * 1024];
__device__ __align__(16) __nv_bfloat16 g_w2hi[4 * 64 * 512];
__device__ __align__(16) __nv_bfloat16 g_w2lo[4 * 64 * 512];

__device__ __constant__ int c_off[7] = {0, 1, 10, 35, 84, 165, 286};

// ---------------- J_l init ----------------
__device__ double dfact(int n) { double r = 1.0; for (int i = 2; i <= n; i++) r *= (double)i; return r; }

__device__ double small_d(int l, int mp, int m) {
    const double ch = 0.70710678118654752440, sh = 0.70710678118654752440;
    double pref = sqrt(dfact(l + mp) * dfact(l - mp) * dfact(l + m) * dfact(l - m));
    int smin = max(0, m - mp), smax = min(l + m, l - mp);
    double tot = 0.0;
    for (int s = smin; s <= smax; s++) {
        double sign = ((mp - m + s) & 1) ? -1.0 : 1.0;
        double denom = dfact(l + m - s) * dfact(s) * dfact(mp - m + s) * dfact(l - mp - s);
        tot += sign / denom * pow(ch, (double)(2 * l + m - mp - 2 * s)) * pow(sh, (double)(mp - m + 2 * s));
    }
    return pref * tot;
}

__device__ void c2r_row(int l, int i, int* col, double* re, double* im, int* cnt) {
    int m = i - l;
    const double s = 0.70710678118654752440;
    if (m < 0) {
        double sgn = (m & 1) ? -1.0 : 1.0;
        col[0] = l + m; re[0] = 0.0; im[0] = s;
        col[1] = l - m; re[1] = 0.0; im[1] = -sgn * s;
        *cnt = 2;
    } else if (m == 0) {
        col[0] = l; re[0] = 1.0; im[0] = 0.0; *cnt = 1;
    } else {
        double sgn = (m & 1) ? -1.0 : 1.0;
        col[0] = l - m; re[0] = s;        im[0] = 0.0;
        col[1] = l + m; re[1] = sgn * s;  im[1] = 0.0;
        *cnt = 2;
    }
}

__global__ void init_jd_kernel() {
    int idx = threadIdx.x;
    if (idx >= 286) return;
    int l = 0;
    while (idx >= c_off[l + 1]) l++;
    int e = idx - c_off[l];
    int sz = 2 * l + 1;
    int i = e / sz, j = e % sz;
    int ca_c[2], cb_c[2], na, nb;
    double ca_re[2], ca_im[2], cb_re[2], cb_im[2];
    c2r_row(l, i, ca_c, ca_re, ca_im, &na);
    c2r_row(l, j, cb_c, cb_re, cb_im, &nb);
    double acc = 0.0;
    for (int a = 0; a < na; a++)
        for (int b = 0; b < nb; b++) {
            double cross = ca_re[a] * cb_re[b] + ca_im[a] * cb_im[b];
            if (cross != 0.0) acc += cross * small_d(l, ca_c[a] - l, cb_c[b] - l);
        }
    g_JD[idx] = (float)acc;
}

// ---------------- Wigner (parallel over l) ----------------
__device__ __forceinline__ void zrot_apply(const float* v, int sz, int l, float ang, float* out) {
    for (int i = 0; i < sz; i++) {
        float f = (float)(l - i);
        float s, c;
        sincosf(f * ang, &s, &c);
        out[i] = c * v[i] + s * v[sz - 1 - i];
    }
}

__global__ void wigner_kernel(const float* __restrict__ angles, const float* __restrict__ item_rep) {
    int t = blockIdx.x * blockDim.x + threadIdx.x;
    if (t >= N_SAMP * REP * 6) return;
    int l = t % 6;
    int nr = t / 6;
    int n = nr / REP, r = nr % REP;
    float a0 = angles[n * 3 + 0], a1 = angles[n * 3 + 1], a2 = angles[n * 3 + 2];
    float v[11], w[11];
    int sz = 2 * l + 1;
    const float* J = &g_JD[c_off[l]];
    for (int i = 0; i < sz; i++) v[i] = item_rep[(l * l + i) * REP + r];
    zrot_apply(v, sz, l, a2, w);
    for (int i = 0; i < sz; i++) { float s = 0.f; for (int j = 0; j < sz; j++) s += J[i * sz + j] * w[j]; v[i] = s; }
    zrot_apply(v, sz, l, a1, w);
    for (int i = 0; i < sz; i++) { float s = 0.f; for (int j = 0; j < sz; j++) s += J[i * sz + j] * w[j]; v[i] = s; }
    zrot_apply(v, sz, l, a0, w);
    for (int i = 0; i < sz; i++) g_item[n * FEAT + (l * l + i) * REP + r] = w[i];
}

// ---------------- dense: relu(item@w0+b0) -> NHWC bf16 hi/lo ----------------
__global__ __launch_bounds__(256) void dense_kernel(const float* __restrict__ A,
                                                    const float* __restrict__ B,
                                                    const float* __restrict__ bias,
                                                    __nv_bfloat16* __restrict__ Chi,
                                                    __nv_bfloat16* __restrict__ Clo) {
    __shared__ float As[8][68];
    __shared__ float Bs[8][64];
    int tid = threadIdx.x;
    int bn = blockIdx.x, bm = blockIdx.y;
    int tx = tid & 15, ty = tid >> 4;
    u64 accp[4][2];
#pragma unroll
    for (int i = 0; i < 4; i++) { accp[i][0] = 0ull; accp[i][1] = 0ull; }

    int ka = tid & 7, ma = tid >> 3;
    int kb = tid >> 6, nb = tid & 63;
    const float* Ab = A + (size_t)(bm * 64) * FEAT;
    const float* Bb = B + bn * 64;

    for (int k0 = 0; k0 < FEAT; k0 += 8) {
        __syncthreads();
        As[ka][ma]      = Ab[(size_t)ma * FEAT + k0 + ka];
        As[ka][ma + 32] = Ab[(size_t)(ma + 32) * FEAT + k0 + ka];
        Bs[kb][nb]      = Bb[(size_t)(k0 + kb) * DENSE_N + nb];
        Bs[kb + 4][nb]  = Bb[(size_t)(k0 + kb + 4) * DENSE_N + nb];
        __syncthreads();
#pragma unroll
        for (int k = 0; k < 8; k++) {
            float4 a4 = *(const float4*)&As[k][ty * 4];
            ulonglong2 b2 = *(const ulonglong2*)&Bs[k][tx * 4];
            u64 ab[4] = {bcast2(a4.x), bcast2(a4.y), bcast2(a4.z), bcast2(a4.w)};
#pragma unroll
            for (int i = 0; i < 4; i++) {
                accp[i][0] = fma2(ab[i], b2.x, accp[i][0]);
                accp[i][1] = fma2(ab[i], b2.y, accp[i][1]);
            }
        }
    }
    float4 bi4 = *(const float4*)&bias[bn * 64 + tx * 4];
    float bv[4] = {bi4.x, bi4.y, bi4.z, bi4.w};
#pragma unroll
    for (int i = 0; i < 4; i++) {
        int m = bm * 64 + ty * 4 + i;
        float2 p0 = unpk2(accp[i][0]);
        float2 p1 = unpk2(accp[i][1]);
        float vals[4] = {fmaxf(p0.x + bv[0], 0.f), fmaxf(p0.y + bv[1], 0.f),
                         fmaxf(p1.x + bv[2], 0.f), fmaxf(p1.y + bv[3], 0.f)};
#pragma unroll
        for (int jj = 0; jj < 4; jj++) {
            int pix = tx * 4 + jj;
            size_t idx = ((size_t)m * 64 + pix) * 256 + bn;
            __nv_bfloat16 h = __float2bfloat16(vals[jj]);
            Chi[idx] = h;
            Clo[idx] = __float2bfloat16(vals[jj] - __bfloat162float(h));
        }
    }
}

// ---------------- weight repack + bf16 split: [parity][co][k=(tap,ci)] --------
__global__ void repack_w_kernel(const float* __restrict__ w, __nv_bfloat16* __restrict__ bhi,
                                __nv_bfloat16* __restrict__ blo, int COUT, int CIN) {
    int idx = blockIdx.x * 256 + threadIdx.x;
    int K = 4 * CIN;
    int total = 4 * COUT * K;
    if (idx >= total) return;
    int p = idx / (COUT * K);
    int r = idx % (COUT * K);
    int co = r / K;
    int k = r % K;
    int t = k / CIN, ci = k % CIN;
    int dy = t >> 1, dx = t & 1, ry = p >> 1, rx = p & 1;
    float v = w[((co * CIN + ci) * 4 + (2 * dy + ry)) * 4 + (2 * dx + rx)];
    __nv_bfloat16 h = __float2bfloat16(v);
    bhi[idx] = h;
    blo[idx] = __float2bfloat16(v - __bfloat162float(h));
}

// ---------------- HMMA implicit-GEMM deconv (cp.async double-buffered) ----------
template <int CIN, int COUT, int HIN, bool OUT_BF16>
__global__ __launch_bounds__(256) void deconv_mma_kernel(
    const __nv_bfloat16* __restrict__ in_hi, const __nv_bfloat16* __restrict__ in_lo,
    const __nv_bfloat16* __restrict__ w_hi,  const __nv_bfloat16* __restrict__ w_lo,
    __nv_bfloat16* __restrict__ out_hi, __nv_bfloat16* __restrict__ out_lo,
    float* __restrict__ out_f) {
    constexpr int NSTAGE = 4 * CIN / 64;
    constexpr int HOUT = 2 * HIN;
    constexpr int PIX = HIN * HIN;
    constexpr int SROW = 144;
    constexpr int ABYTES = 128 * SROW;
    constexpr int BBYTES = COUT * SROW;
    constexpr int STAGEB = 2 * ABYTES + 2 * BBYTES;
    constexpr int NF8 = COUT / 16;
    constexpr int NG  = COUT / 32;
    constexpr int BTASK = COUT * 8 / 256;   // B cp16 tasks per thread

    extern __shared__ __align__(16) char smem[];
    const u32 u0 = smem_to_u32(smem);

    const int tid = threadIdx.x;
    const int wid = tid >> 5;
    const int lid = tid & 31;
    const int wm = wid >> 1;
    const int wn = wid & 1;
    const int m0 = blockIdx.x * 128;
    const int par = blockIdx.y;
    const int ry = par >> 1, rx = par & 1;

    // per-thread A-copy geometry (4 tasks of 16B x {hi,lo})
    int a_row[4], a_u4[4], a_qy[4], a_qx[4];
    size_t a_nb[4];
#pragma unroll
    for (int k = 0; k < 4; k++) {
        int idx = tid + k * 256;
        a_row[k] = idx >> 3;
        a_u4[k]  = idx & 7;
        int r = m0 + a_row[k];
        int n = r / PIX, q = r % PIX;
        a_qy[k] = q / HIN;
        a_qx[k] = q % HIN;
        a_nb[k] = (size_t)n * PIX * CIN;
    }

    auto load_stage = [&](int s, int buf) {
        const int t_tap = s / (CIN / 64);
        const int ci0   = (s % (CIN / 64)) * 64;
        const int dy = t_tap >> 1, dx = t_tap & 1;
        const u32 uAh = u0 + buf * STAGEB;
        const u32 uAl = uAh + ABYTES;
        const u32 uBh = uAh + 2 * ABYTES;
        const u32 uBl = uBh + BBYTES;
#pragma unroll
        for (int k = 0; k < 4; k++) {
            int y = a_qy[k] + dy - 1 + ry;
            int x = a_qx[k] + dx - 1 + rx;
            bool p = (y >= 0) && (y < HIN) && (x >= 0) && (x < HIN);
            int yc = p ? y : 0, xc = p ? x : 0;
            size_t base = a_nb[k] + ((size_t)yc * HIN + xc) * CIN + ci0 + a_u4[k] * 8;
            u32 doff = a_row[k] * SROW + a_u4[k] * 16;
            cp16(uAh + doff, &in_hi[base], p);
            cp16(uAl + doff, &in_lo[base], p);
        }
#pragma unroll
        for (int k = 0; k < BTASK; k++) {
            int idx = tid + k * 256;
            int co = idx >> 3, u4 = idx & 7;
            size_t base = ((size_t)par * COUT + co) * (4 * CIN) + s * 64 + u4 * 8;
            u32 doff = co * SROW + u4 * 16;
            cp16(uBh + doff, &w_hi[base], true);
            cp16(uBl + doff, &w_lo[base], true);
        }
        cp_commit();
    };

    const int lrow = lid & 15;
    const int lcol = (lid >> 4) << 4;
    const int aoff0 = (wm * 32 + lrow) * SROW + lcol;
    const int aoff1 = aoff0 + 16 * SROW;
    int boff[NG];
#pragma unroll
    for (int g = 0; g < NG; g++) boff[g] = (wn * (COUT / 2) + g * 16 + lrow) * SROW + lcol;

    float acc[2][NF8][4];
#pragma unroll
    for (int t = 0; t < 2; t++)
#pragma unroll
        for (int f = 0; f < NF8; f++)
#pragma unroll
            for (int j = 0; j < 4; j++) acc[t][f][j] = 0.f;

    load_stage(0, 0);

    for (int s = 0; s < NSTAGE; s++) {
        const int buf = s & 1;
        if (s + 1 < NSTAGE) { load_stage(s + 1, buf ^ 1); cp_wait1(); }
        else                { cp_wait0(); }
        __syncthreads();

        const u32 uAh = u0 + buf * STAGEB;
        const u32 uAl = uAh + ABYTES;
        const u32 uBh = uAh + 2 * ABYTES;
        const u32 uBl = uBh + BBYTES;
#pragma unroll
        for (int ks = 0; ks < 4; ks++) {
            u32 ah[2][4], al[2][4];
            u32 bh[NG][4], bl[NG][4];
            ldsm4(ah[0], uAh + aoff0 + ks * 32);
            ldsm4(ah[1], uAh + aoff1 + ks * 32);
            ldsm4(al[0], uAl + aoff0 + ks * 32);
            ldsm4(al[1], uAl + aoff1 + ks * 32);
#pragma unroll
            for (int g = 0; g < NG; g++) {
                ldsm4(bh[g], uBh + boff[g] + ks * 32);
                ldsm4(bl[g], uBl + boff[g] + ks * 32);
            }
            // term-outermost: consecutive MMAs hit different accumulators
#pragma unroll
            for (int tm = 0; tm < 2; tm++)
#pragma unroll
                for (int g = 0; g < NG; g++)
#pragma unroll
                    for (int h = 0; h < 2; h++)
                        mma16816(acc[tm][g * 2 + h], ah[tm], bh[g][h], bh[g][h + 2]);
#pragma unroll
            for (int tm = 0; tm < 2; tm++)
#pragma unroll
                for (int g = 0; g < NG; g++)
#pragma unroll
                    for (int h = 0; h < 2; h++)
                        mma16816(acc[tm][g * 2 + h], ah[tm], bl[g][h], bl[g][h + 2]);
#pragma unroll
            for (int tm = 0; tm < 2; tm++)
#pragma unroll
                for (int g = 0; g < NG; g++)
#pragma unroll
                    for (int h = 0; h < 2; h++)
                        mma16816(acc[tm][g * 2 + h], al[tm], bh[g][h], bh[g][h + 2]);
        }
        __syncthreads();
    }

    // ---- epilogue: ReLU + NHWC store ----
#pragma unroll
    for (int tm = 0; tm < 2; tm++) {
        int r0 = m0 + wm * 32 + tm * 16 + (lid >> 2);
#pragma unroll
        for (int rr = 0; rr < 2; rr++) {
            int r = r0 + rr * 8;
            int n = r / PIX, q = r % PIX;
            int yo = 2 * (q / HIN) + ry;
            int xo = 2 * (q % HIN) + rx;
            size_t obase = (((size_t)n * HOUT + yo) * HOUT + xo) * COUT;
#pragma unroll
            for (int f = 0; f < NF8; f++) {
                int ch = wn * (COUT / 2) + f * 8 + (lid & 3) * 2;
                float v0 = fmaxf(acc[tm][f][rr * 2 + 0], 0.f);
                float v1 = fmaxf(acc[tm][f][rr * 2 + 1], 0.f);
                if (OUT_BF16) {
                    u32 hp = bf16pack(v0, v1);
                    float2 hf = bf16unpk(hp);
                    u32 lp = bf16pack(v0 - hf.x, v1 - hf.y);
                    *(u32*)&out_hi[obase + ch] = hp;
                    *(u32*)&out_lo[obase + ch] = lp;
                } else {
                    *(float2*)&out_f[obase + ch] = make_float2(v0, v1);
                }
            }
        }
    }
}

// ---------------- deconv3: 64 -> 3, NHWC fp32 input, NCHW output ----------------
__global__ __launch_bounds__(256) void deconv3_kernel(const float* __restrict__ in,
                                                      const float* __restrict__ wgt,
                                                      float* __restrict__ out) {
    int n = blockIdx.x;
    __shared__ float sin_[34 * 34 * 4];
    __shared__ float wsm[3 * 64 * 16 * 2];
    int tid = threadIdx.x;

    for (int idx = tid; idx < 3072; idx += 256) {
        int tap = idx & 15;
        int cc = idx >> 4;
        int co = cc % 3, ci = cc / 3;
        float w = wgt[(co * 64 + ci) * 16 + tap];
        wsm[((ci * 3 + co) * 16 + tap) * 2 + 0] = w;
        wsm[((ci * 3 + co) * 16 + tap) * 2 + 1] = w;
    }

    int qy0 = (tid >> 4) * 2;
    int qx0 = (tid & 15) * 2;
    u64 accp[3][8];
#pragma unroll
    for (int c = 0; c < 3; c++)
#pragma unroll
        for (int i = 0; i < 8; i++) accp[c][i] = 0ull;

    const float* in_n = in + (size_t)n * 1024 * 64;
    for (int ci0 = 0; ci0 < 64; ci0 += 4) {
        __syncthreads();
        for (int idx = tid; idx < 1156; idx += 256) {
            int py = idx / 34, px = idx % 34;
            int y = py - 1, x = px - 1;
            float4 v = make_float4(0.f, 0.f, 0.f, 0.f);
            if (y >= 0 && y < 32 && x >= 0 && x < 32)
                v = *(const float4*)&in_n[(y * 32 + x) * 64 + ci0];
            *(float4*)&sin_[idx * 4] = v;
        }
        __syncthreads();
#pragma unroll 1
        for (int ci = 0; ci < 4; ci++) {
            float iv[4][4];
#pragma unroll
            for (int yy = 0; yy < 4; yy++)
#pragma unroll
                for (int xx = 0; xx < 4; xx++)
                    iv[yy][xx] = sin_[((qy0 + yy) * 34 + qx0 + xx) * 4 + ci];
            u64 ivp2[4][3];
#pragma unroll
            for (int yy = 0; yy < 4; yy++)
#pragma unroll
                for (int xx = 0; xx < 3; xx++)
                    ivp2[yy][xx] = pack2(iv[yy][xx], iv[yy][xx + 1]);
#pragma unroll
            for (int co = 0; co < 3; co++) {
#pragma unroll
                for (int tap = 0; tap < 16; tap++) {
                    const int ky = tap >> 2, kx = tap & 3;
                    const int ry = ky & 1, dy = ky >> 1;
                    const int rx = kx & 1, dx = kx >> 1;
                    u64 wp = *(const u64*)&wsm[(((ci0 + ci) * 3 + co) * 16 + tap) * 2];
#pragma unroll
                    for (int qy = 0; qy < 2; qy++) {
                        const int o = qy * 4 + ry * 2 + rx;
                        accp[co][o] = fma2(wp, ivp2[qy + dy + ry][dx + rx], accp[co][o]);
                    }
                }
            }
        }
    }
    float* out_n = out + (size_t)n * 3 * 4096;
#pragma unroll
    for (int co = 0; co < 3; co++)
#pragma unroll
        for (int qy = 0; qy < 2; qy++)
#pragma unroll
            for (int ry = 0; ry < 2; ry++)
#pragma unroll
                for (int rx = 0; rx < 2; rx++) {
                    float2 v = unpk2(accp[co][qy * 4 + ry * 2 + rx]);
                    int yo = 2 * (qy0 + qy) + ry;
                    int xo0 = 2 * (qx0 + 0) + rx;
                    int xo1 = 2 * (qx0 + 1) + rx;
                    out_n[co * 4096 + yo * 64 + xo0] = v.x;
                    out_n[co * 4096 + yo * 64 + xo1] = v.y;
                }
}

// -----------------------------------------------------------------------------------------
extern "C" void kernel_launch(void* const* d_in, const int* in_sizes, int n_in,
                              void* d_out, int out_size) {
    (void)in_sizes; (void)n_in; (void)out_size;
    const float* angles   = (const float*)d_in[0];
    const float* item_rep = (const float*)d_in[1];
    const float* w0       = (const float*)d_in[2];
    const float* b0       = (const float*)d_in[3];
    const float* w1       = (const float*)d_in[4];
    const float* w2       = (const float*)d_in[5];
    const float* w3       = (const float*)d_in[6];
    float* out = (float*)d_out;

    float *p_item, *p_h2;
    cudaGetSymbolAddress((void**)&p_item, g_item);
    cudaGetSymbolAddress((void**)&p_h2, g_h2);
    __nv_bfloat16 *p_h0hi, *p_h0lo, *p_h1hi, *p_h1lo;
    cudaGetSymbolAddress((void**)&p_h0hi, g_h0hi);
    cudaGetSymbolAddress((void**)&p_h0lo, g_h0lo);
    cudaGetSymbolAddress((void**)&p_h1hi, g_h1hi);
    cudaGetSymbolAddress((void**)&p_h1lo, g_h1lo);
    __nv_bfloat16 *p_w1hi, *p_w1lo, *p_w2hi, *p_w2lo;
    cudaGetSymbolAddress((void**)&p_w1hi, g_w1hi);
    cudaGetSymbolAddress((void**)&p_w1lo, g_w1lo);
    cudaGetSymbolAddress((void**)&p_w2hi, g_w2hi);
    cudaGetSymbolAddress((void**)&p_w2lo, g_w2lo);

    constexpr int SMEM1 = 2 * (2 * 128 * 144 + 2 * 128 * 144);  // 147456
    constexpr int SMEM2 = 2 * (2 * 128 * 144 + 2 * 64 * 144);   // 110592
    cudaFuncSetAttribute(deconv_mma_kernel<256, 128, 8, true>,
                         cudaFuncAttributeMaxDynamicSharedMemorySize, SMEM1);
    cudaFuncSetAttribute(deconv_mma_kernel<128, 64, 16, false>,
                         cudaFuncAttributeMaxDynamicSharedMemorySize, SMEM2);

    init_jd_kernel<<<1, 288>>>();
    repack_w_kernel<<<(4 * 128 * 1024) / 256, 256>>>(w1, p_w1hi, p_w1lo, 128, 256);
    repack_w_kernel<<<(4 * 64 * 512) / 256, 256>>>(w2, p_w2hi, p_w2lo, 64, 128);
    wigner_kernel<<<(N_SAMP * REP * 6 + 127) / 128, 128>>>(angles, item_rep);
    dense_kernel<<<dim3(DENSE_N / 64, N_SAMP / 64), 256>>>(p_item, w0, b0, p_h0hi, p_h0lo);
    deconv_mma_kernel<256, 128, 8, true><<<dim3(1024, 4), 256, SMEM1>>>(
        p_h0hi, p_h0lo, p_w1hi, p_w1lo, p_h1hi, p_h1lo, nullptr);
    deconv_mma_kernel<128, 64, 16, false><<<dim3(4096, 4), 256, SMEM2>>>(
        p_h1hi, p_h1lo, p_w2hi, p_w2lo, nullptr, nullptr, p_h2);
    deconv3_kernel<<<N_SAMP, 256>>>(p_h2, w3, out);
}